// round 3
// baseline (speedup 1.0000x reference)
#include <cuda_runtime.h>

// YOLO v1 loss: pred/target (2048,14,14,30) fp32 -> scalar fp32.
// Memory-bound streaming kernel: stage 128 cells/block into smem via
// coalesced float4 loads, compute per-cell loss, two-stage deterministic
// reduction (block partials -> single-block double reduce).

#define TPB 128
#define CH  30
#define MAX_BLOCKS 8192

__device__ float g_partials[MAX_BLOCKS];

__global__ void __launch_bounds__(TPB) yolo_main_kernel(
    const float* __restrict__ pred,
    const float* __restrict__ tgt,
    int cells)
{
    __shared__ float sp[TPB * CH];   // 15360 B
    __shared__ float st[TPB * CH];   // 15360 B

    const int tid = threadIdx.x;
    const long long base = (long long)blockIdx.x * (TPB * CH);
    const int cell0 = blockIdx.x * TPB;

    // Coalesced staging. Block base is 15360 B aligned relative to the
    // 256B-aligned allocation, so float4 loads are legal.
    int avail = cells - cell0;                 // cells this block actually owns
    if (avail >= TPB) {
        const float4* p4 = reinterpret_cast<const float4*>(pred + base);
        const float4* t4 = reinterpret_cast<const float4*>(tgt + base);
        float4* sp4 = reinterpret_cast<float4*>(sp);
        float4* st4 = reinterpret_cast<float4*>(st);
        #pragma unroll
        for (int i = tid; i < (TPB * CH) / 4; i += TPB) {
            sp4[i] = p4[i];
            st4[i] = t4[i];
        }
    } else {
        int nfl = (avail > 0 ? avail : 0) * CH;
        for (int i = tid; i < nfl; i += TPB) {
            sp[i] = pred[base + i];
            st[i] = tgt[base + i];
        }
    }
    __syncthreads();

    float v = 0.0f;
    if (cell0 + tid < cells) {
        const float* p = sp + tid * CH;
        const float* t = st + tid * CH;
        const float inv14 = 1.0f / 14.0f;

        float conf_t = t[4];
        float coo = (conf_t > 0.0f) ? 1.0f : 0.0f;
        float noo = (conf_t == 0.0f) ? 1.0f : 0.0f;

        // no-object confidence loss (both boxes)
        float d4 = p[4] - t[4];
        float d9 = p[9] - t[9];
        float noo_loss = d4 * d4 + d9 * d9;

        // class loss (channels 10..29)
        float cls = 0.0f;
        #pragma unroll
        for (int c = 10; c < 30; c++) {
            float dc = p[c] - t[c];
            cls += dc * dc;
        }

        // target box 0 -> xyxy
        float t0x1 = t[0] * inv14 - 0.5f * t[2];
        float t0y1 = t[1] * inv14 - 0.5f * t[3];
        float t0x2 = t[0] * inv14 + 0.5f * t[2];
        float t0y2 = t[1] * inv14 + 0.5f * t[3];
        float a2 = (t0x2 - t0x1) * (t0y2 - t0y1);

        float iou[2];
        #pragma unroll
        for (int b = 0; b < 2; b++) {
            const float* bb = p + 5 * b;
            float x1 = bb[0] * inv14 - 0.5f * bb[2];
            float y1 = bb[1] * inv14 - 0.5f * bb[3];
            float x2 = bb[0] * inv14 + 0.5f * bb[2];
            float y2 = bb[1] * inv14 + 0.5f * bb[3];
            float lx = fmaxf(x1, t0x1);
            float ly = fmaxf(y1, t0y1);
            float rx = fminf(x2, t0x2);
            float ry = fminf(y2, t0y2);
            float w = fmaxf(rx - lx, 0.0f);
            float h = fmaxf(ry - ly, 0.0f);
            float inter = w * h;
            float a1 = (x2 - x1) * (y2 - y1);
            iou[b] = inter / (a1 + a2 - inter);
        }

        // argmax with first-max tie-break (jnp.argmax semantics)
        int idx = (iou[1] > iou[0]) ? 1 : 0;
        float max_iou = fmaxf(iou[0], iou[1]);

        const float* pr = p + 5 * idx;
        const float* tr = t + 5 * idx;

        float dconf = pr[4] - max_iou;
        float contain = dconf * dconf;

        float dx = pr[0] - tr[0];
        float dy = pr[1] - tr[1];
        float dw = sqrtf(pr[2]) - sqrtf(tr[2]);
        float dh = sqrtf(pr[3]) - sqrtf(tr[3]);
        float loc = dx * dx + dy * dy + dw * dw + dh * dh;

        float oconf = idx ? p[4] : p[9];   // non-responsible box confidence
        float not_contain = oconf * oconf;

        v = coo * (5.0f * loc + 2.0f * contain + not_contain + cls)
          + 0.5f * noo * noo_loss;
    }

    // warp reduce
    #pragma unroll
    for (int o = 16; o > 0; o >>= 1)
        v += __shfl_down_sync(0xffffffffu, v, o);

    __shared__ float warpsum[TPB / 32];
    if ((tid & 31) == 0) warpsum[tid >> 5] = v;
    __syncthreads();
    if (tid == 0) {
        float s = 0.0f;
        #pragma unroll
        for (int i = 0; i < TPB / 32; i++) s += warpsum[i];
        g_partials[blockIdx.x] = s;
    }
}

__global__ void __launch_bounds__(256) yolo_reduce_kernel(
    float* __restrict__ out, int nblocks, double invN)
{
    const int tid = threadIdx.x;
    double s = 0.0;
    for (int i = tid; i < nblocks; i += 256)
        s += (double)g_partials[i];

    #pragma unroll
    for (int o = 16; o > 0; o >>= 1)
        s += __shfl_down_sync(0xffffffffu, s, o);

    __shared__ double ws[8];
    if ((tid & 31) == 0) ws[tid >> 5] = s;
    __syncthreads();
    if (tid == 0) {
        double tot = 0.0;
        #pragma unroll
        for (int i = 0; i < 8; i++) tot += ws[i];
        out[0] = (float)(tot * invN);
    }
}

extern "C" void kernel_launch(void* const* d_in, const int* in_sizes, int n_in,
                              void* d_out, int out_size)
{
    const float* pred = (const float*)d_in[0];
    const float* tgt  = (const float*)d_in[1];
    float* out = (float*)d_out;

    int total = in_sizes[0];           // 2048*14*14*30
    int cells = total / CH;            // 401408
    int N = cells / (14 * 14);         // 2048
    int blocks = (cells + TPB - 1) / TPB;  // 3136

    yolo_main_kernel<<<blocks, TPB>>>(pred, tgt, cells);
    yolo_reduce_kernel<<<1, 256>>>(out, blocks, 1.0 / (double)N);
}

// round 5
// speedup vs baseline: 1.0326x; 1.0326x over previous
#include <cuda_runtime.h>

// YOLO v1 loss: pred/target (2048,14,14,30) fp32 -> scalar fp32.
// Single-kernel version: streaming compute + deterministic fixed-point
// atomic fan-in (int64), last block writes the scalar and resets state.

#define TPB 128
#define CH  30
#define SCALE_BITS 24

__device__ unsigned long long g_acc = 0ULL;
__device__ unsigned int g_done = 0u;

__global__ void __launch_bounds__(TPB) yolo_fused_kernel(
    const float* __restrict__ pred,
    const float* __restrict__ tgt,
    float* __restrict__ out,
    int cells, float invN)
{
    __shared__ float sp[TPB * CH];   // 15360 B
    __shared__ float st[TPB * CH];   // 15360 B

    const int tid = threadIdx.x;
    const long long base = (long long)blockIdx.x * (TPB * CH);
    const int cell0 = blockIdx.x * TPB;

    // Coalesced staging: 15360 B per tensor per block via float4.
    int avail = cells - cell0;
    if (avail >= TPB) {
        const float4* p4 = reinterpret_cast<const float4*>(pred + base);
        const float4* t4 = reinterpret_cast<const float4*>(tgt + base);
        float4* sp4 = reinterpret_cast<float4*>(sp);
        float4* st4 = reinterpret_cast<float4*>(st);
        #pragma unroll
        for (int i = tid; i < (TPB * CH) / 4; i += TPB) {
            sp4[i] = p4[i];
            st4[i] = t4[i];
        }
    } else {
        int nfl = (avail > 0 ? avail : 0) * CH;
        for (int i = tid; i < nfl; i += TPB) {
            sp[i] = pred[base + i];
            st[i] = tgt[base + i];
        }
    }
    __syncthreads();

    float v = 0.0f;
    if (cell0 + tid < cells) {
        const float* p = sp + tid * CH;
        const float* t = st + tid * CH;
        const float inv14 = 1.0f / 14.0f;

        float conf_t = t[4];
        float coo = (conf_t > 0.0f) ? 1.0f : 0.0f;
        float noo = (conf_t == 0.0f) ? 1.0f : 0.0f;

        // no-object confidence loss (both boxes)
        float d4 = p[4] - t[4];
        float d9 = p[9] - t[9];
        float noo_loss = d4 * d4 + d9 * d9;

        // class loss (channels 10..29)
        float cls = 0.0f;
        #pragma unroll
        for (int c = 10; c < 30; c++) {
            float dc = p[c] - t[c];
            cls += dc * dc;
        }

        // target box 0 -> xyxy
        float t0x1 = t[0] * inv14 - 0.5f * t[2];
        float t0y1 = t[1] * inv14 - 0.5f * t[3];
        float t0x2 = t[0] * inv14 + 0.5f * t[2];
        float t0y2 = t[1] * inv14 + 0.5f * t[3];
        float a2 = (t0x2 - t0x1) * (t0y2 - t0y1);

        float iou[2];
        #pragma unroll
        for (int b = 0; b < 2; b++) {
            const float* bb = p + 5 * b;
            float x1 = bb[0] * inv14 - 0.5f * bb[2];
            float y1 = bb[1] * inv14 - 0.5f * bb[3];
            float x2 = bb[0] * inv14 + 0.5f * bb[2];
            float y2 = bb[1] * inv14 + 0.5f * bb[3];
            float lx = fmaxf(x1, t0x1);
            float ly = fmaxf(y1, t0y1);
            float rx = fminf(x2, t0x2);
            float ry = fminf(y2, t0y2);
            float w = fmaxf(rx - lx, 0.0f);
            float h = fmaxf(ry - ly, 0.0f);
            float inter = w * h;
            float a1 = (x2 - x1) * (y2 - y1);
            iou[b] = inter / (a1 + a2 - inter);
        }

        // argmax with first-max tie-break (jnp.argmax semantics)
        int idx = (iou[1] > iou[0]) ? 1 : 0;
        float max_iou = fmaxf(iou[0], iou[1]);

        const float* pr = p + 5 * idx;
        const float* tr = t + 5 * idx;

        float dconf = pr[4] - max_iou;
        float contain = dconf * dconf;

        float dx = pr[0] - tr[0];
        float dy = pr[1] - tr[1];
        float dw = sqrtf(pr[2]) - sqrtf(tr[2]);
        float dh = sqrtf(pr[3]) - sqrtf(tr[3]);
        float loc = dx * dx + dy * dy + dw * dw + dh * dh;

        float oconf = idx ? p[4] : p[9];   // non-responsible box confidence
        float not_contain = oconf * oconf;

        v = coo * (5.0f * loc + 2.0f * contain + not_contain + cls)
          + 0.5f * noo * noo_loss;
    }

    // warp reduce (float)
    #pragma unroll
    for (int o = 16; o > 0; o >>= 1)
        v += __shfl_down_sync(0xffffffffu, v, o);

    __shared__ float warpsum[TPB / 32];
    if ((tid & 31) == 0) warpsum[tid >> 5] = v;
    __syncthreads();

    if (tid == 0) {
        double s = 0.0;
        #pragma unroll
        for (int i = 0; i < TPB / 32; i++) s += (double)warpsum[i];

        // fixed-point contribution (all loss terms are >= 0)
        unsigned long long q =
            (unsigned long long)__double2ll_rn(s * (double)(1 << SCALE_BITS));
        atomicAdd(&g_acc, q);
        __threadfence();

        unsigned int ticket = atomicAdd(&g_done, 1u);
        if (ticket == gridDim.x - 1) {
            // all prior g_acc additions are visible (fence-before-ticket)
            unsigned long long tot = atomicAdd(&g_acc, 0ULL);
            out[0] = (float)((double)tot *
                             (1.0 / (double)(1 << SCALE_BITS)) * (double)invN);
            // reset for next graph replay
            g_acc = 0ULL;
            g_done = 0u;
        }
    }
}

extern "C" void kernel_launch(void* const* d_in, const int* in_sizes, int n_in,
                              void* d_out, int out_size)
{
    const float* pred = (const float*)d_in[0];
    const float* tgt  = (const float*)d_in[1];
    float* out = (float*)d_out;

    int total = in_sizes[0];           // 2048*14*14*30
    int cells = total / CH;            // 401408
    int N = cells / (14 * 14);         // 2048
    int blocks = (cells + TPB - 1) / TPB;  // 3136

    yolo_fused_kernel<<<blocks, TPB>>>(pred, tgt, out, cells, 1.0f / (float)N);
}